// round 11
// baseline (speedup 1.0000x reference)
#include <cuda_runtime.h>
#include <cuda_fp16.h>
#include <math.h>

#define B_ 256
#define V_ 128
#define M_ 256
#define H_ 1024
#define TD 10
#define IN_DIM 35840          // (V + TD + 1 + 1) * M
#define KC 8                  // split-K chunks
#define KPC (IN_DIM / KC)     // 4480
#define BM 128
#define BN 64                 // per weight matrix (dual-gemm per CTA)
#define BK 32
#define NITER (KPC / BK)      // 140
#define PAB 80                // A smem row pitch bytes (32 halves + pad)
#define PBB 80                // B smem n-row pitch bytes (32 halves + pad)
#define A_STG (BM * PAB)      // 10240
#define B_MAT (BN * PBB)      // 5120
#define B_STG (2 * B_MAT)     // 10240 (W1 + Wg)
#define B_OFF (3 * A_STG)     // 30720 (A ring: 3 stages)
#define SMEM_BYTES (B_OFF + 2 * B_STG)   // 51200 -> 2 CTAs/SM

// ---------------- device scratch (no allocations allowed) ----------------
__device__ __half g_predh[B_ * IN_DIM];     // fp16-rounded features
__device__ float g_h1p[KC][B_ * H_];        // split-K partials, GEMM 1
__device__ float g_hgp[KC][B_ * H_];        // split-K partials, gate GEMM
__device__ float g_h[B_ * H_];              // gated hidden
__device__ float g_opart[4][B_ * V_];       // out-gemm k-split partials

__device__ __forceinline__ void mma16(float c[4], const unsigned a[4],
                                      unsigned b0, unsigned b1) {
    asm volatile(
        "mma.sync.aligned.m16n8k16.row.col.f32.f16.f16.f32 "
        "{%0,%1,%2,%3}, {%4,%5,%6,%7}, {%8,%9}, {%0,%1,%2,%3};\n"
        : "+f"(c[0]), "+f"(c[1]), "+f"(c[2]), "+f"(c[3])
        : "r"(a[0]), "r"(a[1]), "r"(a[2]), "r"(a[3]), "r"(b0), "r"(b1));
}

__device__ __forceinline__ unsigned packh2(float lo, float hi) {
    unsigned r;
    asm("cvt.rn.f16x2.f32 %0, %1, %2;" : "=r"(r) : "f"(hi), "f"(lo));
    return r;   // low 16 bits = lo (even k), high = hi (odd k)
}

#define CP16(dst, src) \
    asm volatile("cp.async.cg.shared.global [%0], [%1], 16;" :: "r"(dst), "l"(src))
#define CPCOMMIT() asm volatile("cp.async.commit_group;" ::: "memory")
#define CPWAIT1()  asm volatile("cp.async.wait_group 1;" ::: "memory")
#define STS64(addr, r0, r1) \
    asm volatile("st.shared.v2.b32 [%0], {%1,%2};" :: "r"(addr), "r"(r0), "r"(r1) : "memory")

// ---------------- kernel 1: preprocessing (roll + stable sort + features) ---
__global__ __launch_bounds__(256) void prep_kernel(
    const float* __restrict__ x, const float* __restrict__ memory,
    const void* __restrict__ timings_raw, const float* __restrict__ msurp,
    const float* __restrict__ lastpred) {
    int b = blockIdx.x, s = threadIdx.x;
    __shared__ int t_sh[M_];
    __shared__ int rank_sh[M_];
    __shared__ float red[256];
    __shared__ int hi_nonzero;

    if (s == 0) hi_nonzero = 0;
    __syncthreads();
    {   // dtype sniff: int64 -> high 32-bit words of first 256 entries all 0
        const unsigned* w32 = (const unsigned*)timings_raw;
        if (w32[2 * s + 1] != 0u) hi_nonzero = 1;
    }
    __syncthreads();
    int is64 = !hi_nonzero;

    int t;
    if (s == 0) {
        t = 0;
    } else {
        int src = b * M_ + s - 1;
        long long tv = is64 ? ((const long long*)timings_raw)[src]
                            : (long long)((const int*)timings_raw)[src];
        t = (int)tv + 1;
    }
    t_sh[s] = t;
    __syncthreads();

    int r = 0, mx = 0;
#pragma unroll 8
    for (int j = 0; j < M_; ++j) {
        int tj = t_sh[j];
        mx = max(mx, tj);
        r += (tj < t) || (tj == t && j < s);
    }
    rank_sh[s] = r;

    float pv = (s < V_) ? x[b * V_ + s] * lastpred[b * V_ + s] : 0.f;
    red[s] = pv;
    __syncthreads();
    for (int off = 128; off; off >>= 1) {
        if (s < off) red[s] += red[s + off];
        __syncthreads();
    }
    float surprise = -logf(red[0] + 1e-8f);

    float invd = 1.f / ((float)mx + 1.f);
    __half* base = g_predh + (size_t)b * IN_DIM;

#pragma unroll
    for (int d = 0; d < TD; ++d)
        base[M_ * V_ + r * TD + d] = __float2half_rn((float)((t >> d) & 1));
    base[M_ * V_ + M_ * TD + r] = __float2half_rn((float)t * invd);
    float sv = (s == 0) ? surprise : msurp[b * M_ + s - 1] * 0.99f;
    base[M_ * V_ + M_ * TD + M_ + r] = __float2half_rn(sv);

    for (int e = s; e < M_ * V_; e += 256) {
        int sl = e >> 7, v = e & (V_ - 1);
        float val = sl ? memory[((size_t)(b * M_ + sl - 1)) * V_ + v]
                       : x[b * V_ + v];
        base[rank_sh[sl] * V_ + v] = __float2half_rn(val);
    }
}

// ------- kernel 2: fused dual FP16 GEMM; B converted to fp16 [n][k] ---------
// A: cp.async 3-stage ring. B: LDG fp32 (2 stages ahead) -> half2 regs ->
// STS into [n][k] fp16 double buffer. Inner loop: pure LDS.32 + HMMA.
__global__ __launch_bounds__(256, 2) void gemm_kernel(
    const float* __restrict__ W1, const float* __restrict__ Wg) {
    extern __shared__ char smem[];
    const int tid = threadIdx.x, lane = tid & 31, warp = tid >> 5;
    const int wm = warp >> 1, wn = warp & 1;  // 4x2 warp grid, warp tile 32x32
    const int g = lane >> 2, q = lane & 3;
    const int n0 = blockIdx.x * BN;
    const int bm0 = blockIdx.y * BM;
    const int z = blockIdx.z;
    const int k0 = z * KPC;

    const unsigned sb = (unsigned)__cvta_generic_to_shared(smem);

    // ---- A cp.async map: 2 x 16B chunks/thread/stage
    const __half* asrc[2]; unsigned adst[2];
#pragma unroll
    for (int i = 0; i < 2; ++i) {
        int c = tid + i * 256;                   // 0..511
        int row = c >> 2, col4 = c & 3;          // 128 rows x 4 chunks (64B/row)
        asrc[i] = g_predh + (size_t)(bm0 + row) * IN_DIM + k0 + col4 * 8;
        adst[i] = sb + (unsigned)(row * PAB + col4 * 16);
    }

    // ---- B convert map: thread -> (mat, kq, n4); 4 k-rows x 4 n-cols
    const int matB = tid >> 7;               // 0 = W1, 1 = Wg
    const int kq = tid & 7;                  // k-quad within BK=32
    const int n4 = (tid >> 3) & 15;          // n-quad within BN=64
    const float* wsrc = (matB ? Wg : W1) + (size_t)(k0 + kq * 4) * H_ + n0 + n4 * 4;
    const unsigned bq_base = sb + (unsigned)(B_OFF + matB * B_MAT + kq * 8);

    unsigned bufB[2][8];
    auto ldgB = [&](int s, int buf) {
        const float* p = wsrc + (size_t)s * BK * H_;
        float4 v0 = *(const float4*)(p);
        float4 v1 = *(const float4*)(p + H_);
        float4 v2 = *(const float4*)(p + 2 * H_);
        float4 v3 = *(const float4*)(p + 3 * H_);
        bufB[buf][0] = packh2(v0.x, v1.x); bufB[buf][1] = packh2(v2.x, v3.x);
        bufB[buf][2] = packh2(v0.y, v1.y); bufB[buf][3] = packh2(v2.y, v3.y);
        bufB[buf][4] = packh2(v0.z, v1.z); bufB[buf][5] = packh2(v2.z, v3.z);
        bufB[buf][6] = packh2(v0.w, v1.w); bufB[buf][7] = packh2(v2.w, v3.w);
    };
    auto stsB = [&](int kb) {
        unsigned base = bq_base + (unsigned)((kb & 1) * B_STG);
        const unsigned* bu = bufB[kb & 1];
#pragma unroll
        for (int i = 0; i < 4; ++i)
            STS64(base + (unsigned)((n4 * 4 + i) * PBB), bu[i * 2], bu[i * 2 + 1]);
    };
    auto issueA = [&](int s) {
        unsigned so = (unsigned)((s % 3) * A_STG);
        int kg = s * BK;
        CP16(adst[0] + so, asrc[0] + kg);
        CP16(adst[1] + so, asrc[1] + kg);
    };

    float acc1[2][4][4], accg[2][4][4];
#pragma unroll
    for (int mf = 0; mf < 2; ++mf)
#pragma unroll
        for (int nf = 0; nf < 4; ++nf)
#pragma unroll
            for (int i = 0; i < 4; ++i) { acc1[mf][nf][i] = 0.f; accg[mf][nf][i] = 0.f; }

    // prologue
    ldgB(0, 0); issueA(0); CPCOMMIT();
    ldgB(1, 1); issueA(1); CPCOMMIT();

    for (int kb = 0; kb < NITER; ++kb) {
        stsB(kb);             // slot kb&1 free: its readers sync'd at iter kb-1
        CPWAIT1();            // A stage kb landed (this thread's copies)
        __syncthreads();      // global visibility: A ring slot + B STS
        if (kb + 2 < NITER) {
            ldgB(kb + 2, kb & 1);   // reg buffer just drained by stsB
            issueA(kb + 2);
        }
        CPCOMMIT();           // empty group at tail keeps wait math valid

        const char* As = smem + (kb % 3) * A_STG;
        const char* Bh = smem + B_OFF + (kb & 1) * B_STG;

#pragma unroll
        for (int kk = 0; kk < 2; ++kk) {      // two k16 slabs of BK=32
            unsigned a[2][4];
#pragma unroll
            for (int mf = 0; mf < 2; ++mf) {
                const char* ap = As + (wm * 32 + mf * 16 + g) * PAB + kk * 32 + 4 * q;
                a[mf][0] = *(const unsigned*)(ap);
                a[mf][1] = *(const unsigned*)(ap + 8 * PAB);
                a[mf][2] = *(const unsigned*)(ap + 16);
                a[mf][3] = *(const unsigned*)(ap + 8 * PAB + 16);
            }
            unsigned b1f[4][2], bgf[4][2];
#pragma unroll
            for (int nf = 0; nf < 4; ++nf) {
                int col = wn * 32 + nf * 8 + g;
                const char* p1 = Bh + col * PBB + kk * 32 + 4 * q;
                const char* pg = p1 + B_MAT;
                b1f[nf][0] = *(const unsigned*)(p1);
                b1f[nf][1] = *(const unsigned*)(p1 + 16);   // k+8
                bgf[nf][0] = *(const unsigned*)(pg);
                bgf[nf][1] = *(const unsigned*)(pg + 16);
            }
#pragma unroll
            for (int mf = 0; mf < 2; ++mf)
#pragma unroll
                for (int nf = 0; nf < 4; ++nf) {
                    mma16(acc1[mf][nf], a[mf], b1f[nf][0], b1f[nf][1]);
                    mma16(accg[mf][nf], a[mf], bgf[nf][0], bgf[nf][1]);
                }
        }
    }

    // epilogue: deterministic per-chunk partial writes
    float* o1 = g_h1p[z];
    float* og = g_hgp[z];
#pragma unroll
    for (int mf = 0; mf < 2; ++mf) {
        int row = bm0 + wm * 32 + mf * 16 + g;
#pragma unroll
        for (int nf = 0; nf < 4; ++nf) {
            int col = n0 + wn * 32 + nf * 8 + 2 * q;
            *(float2*)&o1[(size_t)row * H_ + col]       = make_float2(acc1[mf][nf][0], acc1[mf][nf][1]);
            *(float2*)&o1[(size_t)(row + 8) * H_ + col] = make_float2(acc1[mf][nf][2], acc1[mf][nf][3]);
            *(float2*)&og[(size_t)row * H_ + col]       = make_float2(accg[mf][nf][0], accg[mf][nf][1]);
            *(float2*)&og[(size_t)(row + 8) * H_ + col] = make_float2(accg[mf][nf][2], accg[mf][nf][3]);
        }
    }
}

// ---------------- kernel 3: split-K reduce + bias + gate --------------------
__global__ __launch_bounds__(256) void gate_kernel(
    const float* __restrict__ b1, const float* __restrict__ bg) {
    int idx = blockIdx.x * 256 + threadIdx.x;
    float s1 = 0.f, sg = 0.f;
#pragma unroll
    for (int c = 0; c < KC; ++c) { s1 += g_h1p[c][idx]; sg += g_hgp[c][idx]; }
    int j = idx & (H_ - 1);
    float pre = s1 + b1[j];
    float gv = sg + bg[j];
    g_h[idx] = pre * (1.f / (1.f + expf(-gv)));
}

// -------- kernel 4a: h @ W2 partials, 4-way k-split across blocks -----------
__global__ __launch_bounds__(256) void out_part_kernel(
    const float* __restrict__ W2) {
    __shared__ float hs[256];
    __shared__ float part[8 * 132];
    int b = blockIdx.x, kc = blockIdx.y, tid = threadIdx.x;
    int c = tid >> 5, vl = tid & 31, v4 = vl * 4;
    hs[tid] = g_h[b * H_ + kc * 256 + tid];
    __syncthreads();

    const float* wb = W2 + (size_t)(kc * 256 + c * 32) * V_ + v4;
    const float* hp = hs + c * 32;
    float4 a0 = make_float4(0.f, 0.f, 0.f, 0.f);
    float4 a1 = make_float4(0.f, 0.f, 0.f, 0.f);
#pragma unroll 4
    for (int i = 0; i < 32; i += 2) {
        float h0 = hp[i], h1 = hp[i + 1];
        float4 w0 = *(const float4*)(wb + (size_t)i * V_);
        float4 w1 = *(const float4*)(wb + (size_t)(i + 1) * V_);
        a0.x += h0 * w0.x; a0.y += h0 * w0.y; a0.z += h0 * w0.z; a0.w += h0 * w0.w;
        a1.x += h1 * w1.x; a1.y += h1 * w1.y; a1.z += h1 * w1.z; a1.w += h1 * w1.w;
    }
    part[c * 132 + v4 + 0] = a0.x + a1.x;
    part[c * 132 + v4 + 1] = a0.y + a1.y;
    part[c * 132 + v4 + 2] = a0.z + a1.z;
    part[c * 132 + v4 + 3] = a0.w + a1.w;
    __syncthreads();

    if (tid < V_) {
        float s = 0.f;
#pragma unroll
        for (int cc = 0; cc < 8; ++cc) s += part[cc * 132 + tid];
        g_opart[kc][b * V_ + tid] = s;
    }
}

// -------- kernel 4b: reduce out partials + bias -----------------------------
__global__ __launch_bounds__(256) void out_reduce_kernel(
    const float* __restrict__ b2, float* __restrict__ out) {
    int idx = blockIdx.x * 256 + threadIdx.x;    // B*V = 32768
    float s = b2[idx & (V_ - 1)];
#pragma unroll
    for (int kc = 0; kc < 4; ++kc) s += g_opart[kc][idx];
    out[idx] = s;
}

// ---------------- launch ----------------------------------------------------
extern "C" void kernel_launch(void* const* d_in, const int* in_sizes, int n_in,
                              void* d_out, int out_size) {
    const float* x        = (const float*)d_in[0];
    const float* memory   = (const float*)d_in[1];
    const void*  timings  = d_in[2];   // int32 or int64, sniffed on device
    const float* msurp    = (const float*)d_in[3];
    const float* lastpred = (const float*)d_in[4];
    const float* W1       = (const float*)d_in[5];
    const float* b1       = (const float*)d_in[6];
    const float* Wg       = (const float*)d_in[7];
    const float* bg       = (const float*)d_in[8];
    const float* W2       = (const float*)d_in[9];
    const float* b2       = (const float*)d_in[10];
    float* out = (float*)d_out;

    cudaFuncSetAttribute(gemm_kernel, cudaFuncAttributeMaxDynamicSharedMemorySize,
                         SMEM_BYTES);

    prep_kernel<<<B_, 256>>>(x, memory, timings, msurp, lastpred);
    gemm_kernel<<<dim3(H_ / BN, B_ / BM, KC), 256, SMEM_BYTES>>>(W1, Wg);
    gate_kernel<<<(B_ * H_) / 256, 256>>>(b1, bg);
    out_part_kernel<<<dim3(B_, 4), 256>>>(W2);
    out_reduce_kernel<<<(B_ * V_) / 256, 256>>>(b2, out);
}

// round 12
// speedup vs baseline: 1.6677x; 1.6677x over previous
#include <cuda_runtime.h>
#include <cuda_fp16.h>
#include <math.h>

#define B_ 256
#define V_ 128
#define M_ 256
#define H_ 1024
#define TD 10
#define IN_DIM 35840          // (V + TD + 1 + 1) * M
#define KC 8                  // split-K chunks
#define KPC (IN_DIM / KC)     // 4480
#define BM 128
#define BN 64                 // per weight matrix (dual-gemm per CTA)
#define BK 32
#define NITER (KPC / BK)      // 140
#define PAB 80                // A smem row pitch in BYTES (32 halves + 16B pad)
#define PWB 68                // B smem row pitch in floats (272 B)
#define A_STG_BYTES (BM * PAB)                 // 10240
#define B_STG_BYTES (BK * PWB * 4)             // 8704 per mat
#define STG_BYTES (A_STG_BYTES + 2 * B_STG_BYTES)   // 27648
#define SMEM_BYTES (3 * STG_BYTES)             // 82944 -> 2 CTAs/SM

// ---------------- device scratch (no allocations allowed) ----------------
__device__ __half g_predh[B_ * IN_DIM];     // fp16-rounded features
__device__ float g_h1p[KC][B_ * H_];        // split-K partials, GEMM 1
__device__ float g_hgp[KC][B_ * H_];        // split-K partials, gate GEMM
__device__ float g_h[B_ * H_];              // gated hidden
__device__ float g_opart[4][B_ * V_];       // out-gemm k-split partials

__device__ __forceinline__ void mma16(float c[4], const unsigned a[4],
                                      unsigned b0, unsigned b1) {
    asm volatile(
        "mma.sync.aligned.m16n8k16.row.col.f32.f16.f16.f32 "
        "{%0,%1,%2,%3}, {%4,%5,%6,%7}, {%8,%9}, {%0,%1,%2,%3};\n"
        : "+f"(c[0]), "+f"(c[1]), "+f"(c[2]), "+f"(c[3])
        : "r"(a[0]), "r"(a[1]), "r"(a[2]), "r"(a[3]), "r"(b0), "r"(b1));
}

__device__ __forceinline__ unsigned packh2(float lo, float hi) {
    unsigned r;
    asm("cvt.rn.f16x2.f32 %0, %1, %2;" : "=r"(r) : "f"(hi), "f"(lo));
    return r;   // low 16 bits = lo, high = hi
}

#define CP16(dst, src) \
    asm volatile("cp.async.cg.shared.global [%0], [%1], 16;" :: "r"(dst), "l"(src))
#define CPCOMMIT() asm volatile("cp.async.commit_group;" ::: "memory")
#define CPWAIT1()  asm volatile("cp.async.wait_group 1;" ::: "memory")

// ---------------- kernel 1: preprocessing (roll + stable sort + features) ---
__global__ __launch_bounds__(256) void prep_kernel(
    const float* __restrict__ x, const float* __restrict__ memory,
    const void* __restrict__ timings_raw, const float* __restrict__ msurp,
    const float* __restrict__ lastpred) {
    int b = blockIdx.x, s = threadIdx.x;
    __shared__ int t_sh[M_];
    __shared__ int rank_sh[M_];
    __shared__ float red[256];
    __shared__ int hi_nonzero;

    if (s == 0) hi_nonzero = 0;
    __syncthreads();
    {   // dtype sniff: int64 -> high 32-bit words of first 256 entries all 0
        const unsigned* w32 = (const unsigned*)timings_raw;
        if (w32[2 * s + 1] != 0u) hi_nonzero = 1;
    }
    __syncthreads();
    int is64 = !hi_nonzero;

    int t;
    if (s == 0) {
        t = 0;
    } else {
        int src = b * M_ + s - 1;
        long long tv = is64 ? ((const long long*)timings_raw)[src]
                            : (long long)((const int*)timings_raw)[src];
        t = (int)tv + 1;
    }
    t_sh[s] = t;
    __syncthreads();

    int r = 0, mx = 0;
#pragma unroll 8
    for (int j = 0; j < M_; ++j) {
        int tj = t_sh[j];
        mx = max(mx, tj);
        r += (tj < t) || (tj == t && j < s);
    }
    rank_sh[s] = r;

    float pv = (s < V_) ? x[b * V_ + s] * lastpred[b * V_ + s] : 0.f;
    red[s] = pv;
    __syncthreads();
    for (int off = 128; off; off >>= 1) {
        if (s < off) red[s] += red[s + off];
        __syncthreads();
    }
    float surprise = -logf(red[0] + 1e-8f);

    float invd = 1.f / ((float)mx + 1.f);
    __half* base = g_predh + (size_t)b * IN_DIM;

#pragma unroll
    for (int d = 0; d < TD; ++d)
        base[M_ * V_ + r * TD + d] = __float2half_rn((float)((t >> d) & 1));
    base[M_ * V_ + M_ * TD + r] = __float2half_rn((float)t * invd);
    float sv = (s == 0) ? surprise : msurp[b * M_ + s - 1] * 0.99f;
    base[M_ * V_ + M_ * TD + M_ + r] = __float2half_rn(sv);

    for (int e = s; e < M_ * V_; e += 256) {
        int sl = e >> 7, v = e & (V_ - 1);
        float val = sl ? memory[((size_t)(b * M_ + sl - 1)) * V_ + v]
                       : x[b * V_ + v];
        base[rank_sh[sl] * V_ + v] = __float2half_rn(val);
    }
}

// ------- kernel 2: fused dual FP16 GEMM, cp.async 3-stage, 2 CTAs/SM --------
// Warp tile 64x16 per matrix (2x4 warp grid): B smem rereads cut 4x -> 2x.
__global__ __launch_bounds__(256, 2) void gemm_kernel(
    const float* __restrict__ W1, const float* __restrict__ Wg) {
    extern __shared__ char smem[];
    const int tid = threadIdx.x, lane = tid & 31, warp = tid >> 5;
    const int wm = warp >> 2, wn = warp & 3;  // 2x4 warp grid, warp tile 64x16
    const int g = lane >> 2, q = lane & 3;
    const int n0 = blockIdx.x * BN;
    const int bm0 = blockIdx.y * BM;
    const int z = blockIdx.z;
    const int k0 = z * KPC;

    unsigned sb = (unsigned)__cvta_generic_to_shared(smem);

    // cp.async chunk maps: A = 2 chunks/thread, B = 4 chunks/thread (16B each)
    const __half* asrc[2]; unsigned adst[2];
    const float* bsrc[4];  unsigned bdst[4];
#pragma unroll
    for (int i = 0; i < 2; ++i) {
        int c = tid + i * 256;                   // 0..511
        int row = c >> 2, col4 = c & 3;          // 128 rows x 4 chunks (64B/row)
        asrc[i] = g_predh + (size_t)(bm0 + row) * IN_DIM + k0 + col4 * 8;
        adst[i] = (unsigned)(row * PAB + col4 * 16);
    }
#pragma unroll
    for (int i = 0; i < 4; ++i) {
        int c = tid + i * 256;                   // 0..1023
        int mat = c >> 9, rr = c & 511;
        int krow = rr >> 4, cc = rr & 15;        // 32 rows x 16 chunks (256B/row)
        bsrc[i] = (mat ? Wg : W1) + (size_t)(k0 + krow) * H_ + n0 + cc * 4;
        bdst[i] = (unsigned)(A_STG_BYTES + mat * B_STG_BYTES + krow * (PWB * 4) + cc * 16);
    }

    auto issue = [&](int s) {
        unsigned st = sb + (unsigned)((s % 3) * STG_BYTES);
        int kg = s * BK;
#pragma unroll
        for (int i = 0; i < 2; ++i)
            CP16(st + adst[i], asrc[i] + kg);
#pragma unroll
        for (int i = 0; i < 4; ++i)
            CP16(st + bdst[i], bsrc[i] + (size_t)kg * H_);
    };

    float acc1[4][2][4], accg[4][2][4];
#pragma unroll
    for (int mf = 0; mf < 4; ++mf)
#pragma unroll
        for (int nf = 0; nf < 2; ++nf)
#pragma unroll
            for (int i = 0; i < 4; ++i) { acc1[mf][nf][i] = 0.f; accg[mf][nf][i] = 0.f; }

    issue(0); CPCOMMIT();
    issue(1); CPCOMMIT();

    for (int kb = 0; kb < NITER; ++kb) {
        CPWAIT1();            // stage kb landed
        __syncthreads();      // prev-iter reads of slot (kb+2)%3 done
        if (kb + 2 < NITER) issue(kb + 2);
        CPCOMMIT();           // empty group at tail keeps wait math valid

        const char* stg = smem + (kb % 3) * STG_BYTES;
        const __half* As = (const __half*)stg;          // [row][32 halves], pitch 80B
        const float* B1 = (const float*)(stg + A_STG_BYTES);
        const float* Bg = (const float*)(stg + A_STG_BYTES + B_STG_BYTES);

#pragma unroll
        for (int kk = 0; kk < 2; ++kk) {      // two k16 slabs of BK=32
            unsigned a[4][4];
#pragma unroll
            for (int mf = 0; mf < 4; ++mf) {
                const char* ap = (const char*)As
                    + (wm * 64 + mf * 16 + g) * PAB + kk * 32 + 4 * q;
                a[mf][0] = *(const unsigned*)(ap);             // A[g][2q..2q+1]
                a[mf][1] = *(const unsigned*)(ap + 8 * PAB);   // A[g+8]
                a[mf][2] = *(const unsigned*)(ap + 16);        // k+8
                a[mf][3] = *(const unsigned*)(ap + 8 * PAB + 16);
            }
            int kt = kk * 16;
            unsigned b1f[2][2], bgf[2][2];
#pragma unroll
            for (int nf = 0; nf < 2; ++nf) {
                int col = wn * 16 + nf * 8 + g;
                const float* p1 = B1 + (kt + 2 * q) * PWB + col;
                const float* pg = Bg + (kt + 2 * q) * PWB + col;
                b1f[nf][0] = packh2(p1[0],        p1[PWB]);
                b1f[nf][1] = packh2(p1[8 * PWB],  p1[9 * PWB]);
                bgf[nf][0] = packh2(pg[0],        pg[PWB]);
                bgf[nf][1] = packh2(pg[8 * PWB],  pg[9 * PWB]);
            }
#pragma unroll
            for (int mf = 0; mf < 4; ++mf)
#pragma unroll
                for (int nf = 0; nf < 2; ++nf) {
                    mma16(acc1[mf][nf], a[mf], b1f[nf][0], b1f[nf][1]);
                    mma16(accg[mf][nf], a[mf], bgf[nf][0], bgf[nf][1]);
                }
        }
    }

    // epilogue: deterministic per-chunk partial writes
    float* o1 = g_h1p[z];
    float* og = g_hgp[z];
#pragma unroll
    for (int mf = 0; mf < 4; ++mf) {
        int row = bm0 + wm * 64 + mf * 16 + g;
#pragma unroll
        for (int nf = 0; nf < 2; ++nf) {
            int col = n0 + wn * 16 + nf * 8 + 2 * q;
            *(float2*)&o1[(size_t)row * H_ + col]       = make_float2(acc1[mf][nf][0], acc1[mf][nf][1]);
            *(float2*)&o1[(size_t)(row + 8) * H_ + col] = make_float2(acc1[mf][nf][2], acc1[mf][nf][3]);
            *(float2*)&og[(size_t)row * H_ + col]       = make_float2(accg[mf][nf][0], accg[mf][nf][1]);
            *(float2*)&og[(size_t)(row + 8) * H_ + col] = make_float2(accg[mf][nf][2], accg[mf][nf][3]);
        }
    }
}

// ---------------- kernel 3: split-K reduce + bias + gate --------------------
__global__ __launch_bounds__(256) void gate_kernel(
    const float* __restrict__ b1, const float* __restrict__ bg) {
    int idx = blockIdx.x * 256 + threadIdx.x;
    float s1 = 0.f, sg = 0.f;
#pragma unroll
    for (int c = 0; c < KC; ++c) { s1 += g_h1p[c][idx]; sg += g_hgp[c][idx]; }
    int j = idx & (H_ - 1);
    float pre = s1 + b1[j];
    float gv = sg + bg[j];
    g_h[idx] = pre * (1.f / (1.f + expf(-gv)));
}

// -------- kernel 4a: h @ W2 partials, 4-way k-split across blocks -----------
__global__ __launch_bounds__(256) void out_part_kernel(
    const float* __restrict__ W2) {
    __shared__ float hs[256];
    __shared__ float part[8 * 132];
    int b = blockIdx.x, kc = blockIdx.y, tid = threadIdx.x;
    int c = tid >> 5, vl = tid & 31, v4 = vl * 4;
    hs[tid] = g_h[b * H_ + kc * 256 + tid];
    __syncthreads();

    const float* wb = W2 + (size_t)(kc * 256 + c * 32) * V_ + v4;
    const float* hp = hs + c * 32;
    float4 a0 = make_float4(0.f, 0.f, 0.f, 0.f);
    float4 a1 = make_float4(0.f, 0.f, 0.f, 0.f);
#pragma unroll 4
    for (int i = 0; i < 32; i += 2) {
        float h0 = hp[i], h1 = hp[i + 1];
        float4 w0 = *(const float4*)(wb + (size_t)i * V_);
        float4 w1 = *(const float4*)(wb + (size_t)(i + 1) * V_);
        a0.x += h0 * w0.x; a0.y += h0 * w0.y; a0.z += h0 * w0.z; a0.w += h0 * w0.w;
        a1.x += h1 * w1.x; a1.y += h1 * w1.y; a1.z += h1 * w1.z; a1.w += h1 * w1.w;
    }
    part[c * 132 + v4 + 0] = a0.x + a1.x;
    part[c * 132 + v4 + 1] = a0.y + a1.y;
    part[c * 132 + v4 + 2] = a0.z + a1.z;
    part[c * 132 + v4 + 3] = a0.w + a1.w;
    __syncthreads();

    if (tid < V_) {
        float s = 0.f;
#pragma unroll
        for (int cc = 0; cc < 8; ++cc) s += part[cc * 132 + tid];
        g_opart[kc][b * V_ + tid] = s;
    }
}

// -------- kernel 4b: reduce out partials + bias -----------------------------
__global__ __launch_bounds__(256) void out_reduce_kernel(
    const float* __restrict__ b2, float* __restrict__ out) {
    int idx = blockIdx.x * 256 + threadIdx.x;    // B*V = 32768
    float s = b2[idx & (V_ - 1)];
#pragma unroll
    for (int kc = 0; kc < 4; ++kc) s += g_opart[kc][idx];
    out[idx] = s;
}

// ---------------- launch ----------------------------------------------------
extern "C" void kernel_launch(void* const* d_in, const int* in_sizes, int n_in,
                              void* d_out, int out_size) {
    const float* x        = (const float*)d_in[0];
    const float* memory   = (const float*)d_in[1];
    const void*  timings  = d_in[2];   // int32 or int64, sniffed on device
    const float* msurp    = (const float*)d_in[3];
    const float* lastpred = (const float*)d_in[4];
    const float* W1       = (const float*)d_in[5];
    const float* b1       = (const float*)d_in[6];
    const float* Wg       = (const float*)d_in[7];
    const float* bg       = (const float*)d_in[8];
    const float* W2       = (const float*)d_in[9];
    const float* b2       = (const float*)d_in[10];
    float* out = (float*)d_out;

    cudaFuncSetAttribute(gemm_kernel, cudaFuncAttributeMaxDynamicSharedMemorySize,
                         SMEM_BYTES);

    prep_kernel<<<B_, 256>>>(x, memory, timings, msurp, lastpred);
    gemm_kernel<<<dim3(H_ / BN, B_ / BM, KC), 256, SMEM_BYTES>>>(W1, Wg);
    gate_kernel<<<(B_ * H_) / 256, 256>>>(b1, bg);
    out_part_kernel<<<dim3(B_, 4), 256>>>(W2);
    out_reduce_kernel<<<(B_ * V_) / 256, 256>>>(b2, out);
}

// round 13
// speedup vs baseline: 1.7903x; 1.0735x over previous
#include <cuda_runtime.h>
#include <cuda_fp16.h>
#include <math.h>

#define B_ 256
#define V_ 128
#define M_ 256
#define H_ 1024
#define TD 10
#define IN_DIM 35840          // (V + TD + 1 + 1) * M
#define KC 8                  // split-K chunks
#define KPC (IN_DIM / KC)     // 4480
#define BM 128
#define BN 64                 // per weight matrix (dual-gemm per CTA)
#define BK 32
#define NITER (KPC / BK)      // 140
#define PAB 80                // A smem row pitch in BYTES (32 halves + 16B pad)
#define PWB 68                // B smem row pitch in floats (272 B)
#define A_STG_BYTES (BM * PAB)                 // 10240
#define B_STG_BYTES (BK * PWB * 4)             // 8704 per mat
#define STG_BYTES (A_STG_BYTES + 2 * B_STG_BYTES)   // 27648
#define SMEM_BYTES (3 * STG_BYTES)             // 82944 -> 2 CTAs/SM
#define NB 4                  // b-rows batched per out_part block

// ---------------- device scratch (no allocations allowed) ----------------
__device__ __half g_predh[B_ * IN_DIM];     // fp16-rounded features
__device__ float g_h1p[KC][B_ * H_];        // split-K partials, GEMM 1
__device__ float g_hgp[KC][B_ * H_];        // split-K partials, gate GEMM
__device__ float g_opart[4][B_ * V_];       // out-gemm k-split partials

__device__ __forceinline__ void mma16(float c[4], const unsigned a[4],
                                      unsigned b0, unsigned b1) {
    asm volatile(
        "mma.sync.aligned.m16n8k16.row.col.f32.f16.f16.f32 "
        "{%0,%1,%2,%3}, {%4,%5,%6,%7}, {%8,%9}, {%0,%1,%2,%3};\n"
        : "+f"(c[0]), "+f"(c[1]), "+f"(c[2]), "+f"(c[3])
        : "r"(a[0]), "r"(a[1]), "r"(a[2]), "r"(a[3]), "r"(b0), "r"(b1));
}

__device__ __forceinline__ unsigned packh2(float lo, float hi) {
    unsigned r;
    asm("cvt.rn.f16x2.f32 %0, %1, %2;" : "=r"(r) : "f"(hi), "f"(lo));
    return r;   // low 16 bits = lo, high = hi
}

#define LDSM4(r, addr) \
    asm volatile("ldmatrix.sync.aligned.m8n8.x4.shared.b16 {%0,%1,%2,%3}, [%4];" \
        : "=r"((r)[0]), "=r"((r)[1]), "=r"((r)[2]), "=r"((r)[3]) : "r"(addr))

#define CP16(dst, src) \
    asm volatile("cp.async.cg.shared.global [%0], [%1], 16;" :: "r"(dst), "l"(src))
#define CPCOMMIT() asm volatile("cp.async.commit_group;" ::: "memory")
#define CPWAIT1()  asm volatile("cp.async.wait_group 1;" ::: "memory")

// ---------------- kernel 1: preprocessing (roll + stable sort + features) ---
__global__ __launch_bounds__(256) void prep_kernel(
    const float* __restrict__ x, const float* __restrict__ memory,
    const void* __restrict__ timings_raw, const float* __restrict__ msurp,
    const float* __restrict__ lastpred) {
    int b = blockIdx.x, s = threadIdx.x;
    __shared__ int t_sh[M_];
    __shared__ int rank_sh[M_];
    __shared__ float red[256];
    __shared__ int hi_nonzero;

    if (s == 0) hi_nonzero = 0;
    __syncthreads();
    {   // dtype sniff: int64 -> high 32-bit words of first 256 entries all 0
        const unsigned* w32 = (const unsigned*)timings_raw;
        if (w32[2 * s + 1] != 0u) hi_nonzero = 1;
    }
    __syncthreads();
    int is64 = !hi_nonzero;

    int t;
    if (s == 0) {
        t = 0;
    } else {
        int src = b * M_ + s - 1;
        long long tv = is64 ? ((const long long*)timings_raw)[src]
                            : (long long)((const int*)timings_raw)[src];
        t = (int)tv + 1;
    }
    t_sh[s] = t;
    __syncthreads();

    int r = 0, mx = 0;
#pragma unroll 8
    for (int j = 0; j < M_; ++j) {
        int tj = t_sh[j];
        mx = max(mx, tj);
        r += (tj < t) || (tj == t && j < s);
    }
    rank_sh[s] = r;

    float pv = (s < V_) ? x[b * V_ + s] * lastpred[b * V_ + s] : 0.f;
    red[s] = pv;
    __syncthreads();
    for (int off = 128; off; off >>= 1) {
        if (s < off) red[s] += red[s + off];
        __syncthreads();
    }
    float surprise = -logf(red[0] + 1e-8f);

    float invd = 1.f / ((float)mx + 1.f);
    __half* base = g_predh + (size_t)b * IN_DIM;

#pragma unroll
    for (int d = 0; d < TD; ++d)
        base[M_ * V_ + r * TD + d] = __float2half_rn((float)((t >> d) & 1));
    base[M_ * V_ + M_ * TD + r] = __float2half_rn((float)t * invd);
    float sv = (s == 0) ? surprise : msurp[b * M_ + s - 1] * 0.99f;
    base[M_ * V_ + M_ * TD + M_ + r] = __float2half_rn(sv);

    for (int e = s; e < M_ * V_; e += 256) {
        int sl = e >> 7, v = e & (V_ - 1);
        float val = sl ? memory[((size_t)(b * M_ + sl - 1)) * V_ + v]
                       : x[b * V_ + v];
        base[rank_sh[sl] * V_ + v] = __float2half_rn(val);
    }
}

// ------- kernel 2: fused dual FP16 GEMM, cp.async 3-stage, LDSM A ----------
__global__ __launch_bounds__(256, 2) void gemm_kernel(
    const float* __restrict__ W1, const float* __restrict__ Wg) {
    extern __shared__ char smem[];
    const int tid = threadIdx.x, lane = tid & 31, warp = tid >> 5;
    const int wm = warp >> 2, wn = warp & 3;  // 2x4 warp grid, warp tile 64x16
    const int g = lane >> 2, q = lane & 3;
    const int n0 = blockIdx.x * BN;
    const int bm0 = blockIdx.y * BM;
    const int z = blockIdx.z;
    const int k0 = z * KPC;

    unsigned sb = (unsigned)__cvta_generic_to_shared(smem);

    // LDSM lane address precompute (relative to stage A base):
    // matrix mi=lane>>3: rows +8*(mi&1), k-bytes +16*(mi>>1); row within = lane&7
    const int mi = lane >> 3;
    const int abase_lane = (wm * 64 + (mi & 1) * 8 + (lane & 7)) * PAB + (mi >> 1) * 16;

    // cp.async chunk maps: A = 2 chunks/thread, B = 4 chunks/thread (16B each)
    const __half* asrc[2]; unsigned adst[2];
    const float* bsrc[4];  unsigned bdst[4];
#pragma unroll
    for (int i = 0; i < 2; ++i) {
        int c = tid + i * 256;                   // 0..511
        int row = c >> 2, col4 = c & 3;          // 128 rows x 4 chunks (64B/row)
        asrc[i] = g_predh + (size_t)(bm0 + row) * IN_DIM + k0 + col4 * 8;
        adst[i] = (unsigned)(row * PAB + col4 * 16);
    }
#pragma unroll
    for (int i = 0; i < 4; ++i) {
        int c = tid + i * 256;                   // 0..1023
        int mat = c >> 9, rr = c & 511;
        int krow = rr >> 4, cc = rr & 15;        // 32 rows x 16 chunks (256B/row)
        bsrc[i] = (mat ? Wg : W1) + (size_t)(k0 + krow) * H_ + n0 + cc * 4;
        bdst[i] = (unsigned)(A_STG_BYTES + mat * B_STG_BYTES + krow * (PWB * 4) + cc * 16);
    }

    auto issue = [&](int s) {
        unsigned st = sb + (unsigned)((s % 3) * STG_BYTES);
        int kg = s * BK;
#pragma unroll
        for (int i = 0; i < 2; ++i)
            CP16(st + adst[i], asrc[i] + kg);
#pragma unroll
        for (int i = 0; i < 4; ++i)
            CP16(st + bdst[i], bsrc[i] + (size_t)kg * H_);
    };

    float acc1[4][2][4], accg[4][2][4];
#pragma unroll
    for (int mf = 0; mf < 4; ++mf)
#pragma unroll
        for (int nf = 0; nf < 2; ++nf)
#pragma unroll
            for (int i = 0; i < 4; ++i) { acc1[mf][nf][i] = 0.f; accg[mf][nf][i] = 0.f; }

    issue(0); CPCOMMIT();
    issue(1); CPCOMMIT();

    for (int kb = 0; kb < NITER; ++kb) {
        CPWAIT1();            // stage kb landed
        __syncthreads();      // prev-iter reads of slot (kb+2)%3 done
        if (kb + 2 < NITER) issue(kb + 2);
        CPCOMMIT();           // empty group at tail keeps wait math valid

        const unsigned stgoff = (unsigned)((kb % 3) * STG_BYTES);
        const char* stg = smem + (kb % 3) * STG_BYTES;
        const float* B1 = (const float*)(stg + A_STG_BYTES);
        const float* Bg = (const float*)(stg + A_STG_BYTES + B_STG_BYTES);
        const unsigned abase = sb + stgoff + (unsigned)abase_lane;

#pragma unroll
        for (int kk = 0; kk < 2; ++kk) {      // two k16 slabs of BK=32
            unsigned a[4][4];
#pragma unroll
            for (int mf = 0; mf < 4; ++mf)
                LDSM4(a[mf], abase + (unsigned)(mf * 16 * PAB + kk * 32));
            int kt = kk * 16;
            unsigned b1f[2][2], bgf[2][2];
#pragma unroll
            for (int nf = 0; nf < 2; ++nf) {
                int col = wn * 16 + nf * 8 + g;
                const float* p1 = B1 + (kt + 2 * q) * PWB + col;
                const float* pg = Bg + (kt + 2 * q) * PWB + col;
                b1f[nf][0] = packh2(p1[0],        p1[PWB]);
                b1f[nf][1] = packh2(p1[8 * PWB],  p1[9 * PWB]);
                bgf[nf][0] = packh2(pg[0],        pg[PWB]);
                bgf[nf][1] = packh2(pg[8 * PWB],  pg[9 * PWB]);
            }
#pragma unroll
            for (int mf = 0; mf < 4; ++mf)
#pragma unroll
                for (int nf = 0; nf < 2; ++nf) {
                    mma16(acc1[mf][nf], a[mf], b1f[nf][0], b1f[nf][1]);
                    mma16(accg[mf][nf], a[mf], bgf[nf][0], bgf[nf][1]);
                }
        }
    }

    // epilogue: deterministic per-chunk partial writes
    float* o1 = g_h1p[z];
    float* og = g_hgp[z];
#pragma unroll
    for (int mf = 0; mf < 4; ++mf) {
        int row = bm0 + wm * 64 + mf * 16 + g;
#pragma unroll
        for (int nf = 0; nf < 2; ++nf) {
            int col = n0 + wn * 16 + nf * 8 + 2 * q;
            *(float2*)&o1[(size_t)row * H_ + col]       = make_float2(acc1[mf][nf][0], acc1[mf][nf][1]);
            *(float2*)&o1[(size_t)(row + 8) * H_ + col] = make_float2(acc1[mf][nf][2], acc1[mf][nf][3]);
            *(float2*)&og[(size_t)row * H_ + col]       = make_float2(accg[mf][nf][0], accg[mf][nf][1]);
            *(float2*)&og[(size_t)(row + 8) * H_ + col] = make_float2(accg[mf][nf][2], accg[mf][nf][3]);
        }
    }
}

// ---- kernel 3: fused gate + h @ W2 partials (NB=4 b-rows per block) --------
__global__ __launch_bounds__(256) void out_part_kernel(
    const float* __restrict__ W2, const float* __restrict__ b1,
    const float* __restrict__ bg) {
    __shared__ float hs[NB][256];
    __shared__ float part[NB][8 * 132];
    int bg0 = blockIdx.x, kc = blockIdx.y, tid = threadIdx.x;
    int b0 = bg0 * NB;
    int j = kc * 256 + tid;                    // h index within H
    float bb1 = b1[j], bbg = bg[j];

    // gate(sum of split-K partials) inline, chunk order fixed (deterministic)
#pragma unroll
    for (int nb = 0; nb < NB; ++nb) {
        int idx = (b0 + nb) * H_ + j;
        float s1 = 0.f, sg = 0.f;
#pragma unroll
        for (int c = 0; c < KC; ++c) { s1 += g_h1p[c][idx]; sg += g_hgp[c][idx]; }
        float pre = s1 + bb1;
        float gv = sg + bbg;
        hs[nb][tid] = pre * (1.f / (1.f + expf(-gv)));
    }
    __syncthreads();

    int c = tid >> 5, vl = tid & 31, v4 = vl * 4;
    const float* wb = W2 + (size_t)(kc * 256 + c * 32) * V_ + v4;
    float4 acc[NB];
#pragma unroll
    for (int nb = 0; nb < NB; ++nb) acc[nb] = make_float4(0.f, 0.f, 0.f, 0.f);
#pragma unroll 4
    for (int i = 0; i < 32; ++i) {
        float4 w = *(const float4*)(wb + (size_t)i * V_);
#pragma unroll
        for (int nb = 0; nb < NB; ++nb) {
            float h = hs[nb][c * 32 + i];
            acc[nb].x += h * w.x; acc[nb].y += h * w.y;
            acc[nb].z += h * w.z; acc[nb].w += h * w.w;
        }
    }
#pragma unroll
    for (int nb = 0; nb < NB; ++nb)
        *(float4*)&part[nb][c * 132 + v4] = acc[nb];
    __syncthreads();

    if (tid < V_) {
#pragma unroll
        for (int nb = 0; nb < NB; ++nb) {
            float s = 0.f;
#pragma unroll
            for (int cc = 0; cc < 8; ++cc) s += part[nb][cc * 132 + tid];
            g_opart[kc][(b0 + nb) * V_ + tid] = s;
        }
    }
}

// -------- kernel 4: reduce out partials + bias ------------------------------
__global__ __launch_bounds__(256) void out_reduce_kernel(
    const float* __restrict__ b2, float* __restrict__ out) {
    int idx = blockIdx.x * 256 + threadIdx.x;    // B*V = 32768
    float s = b2[idx & (V_ - 1)];
#pragma unroll
    for (int kc = 0; kc < 4; ++kc) s += g_opart[kc][idx];
    out[idx] = s;
}

// ---------------- launch ----------------------------------------------------
extern "C" void kernel_launch(void* const* d_in, const int* in_sizes, int n_in,
                              void* d_out, int out_size) {
    const float* x        = (const float*)d_in[0];
    const float* memory   = (const float*)d_in[1];
    const void*  timings  = d_in[2];   // int32 or int64, sniffed on device
    const float* msurp    = (const float*)d_in[3];
    const float* lastpred = (const float*)d_in[4];
    const float* W1       = (const float*)d_in[5];
    const float* b1       = (const float*)d_in[6];
    const float* Wg       = (const float*)d_in[7];
    const float* bg       = (const float*)d_in[8];
    const float* W2       = (const float*)d_in[9];
    const float* b2       = (const float*)d_in[10];
    float* out = (float*)d_out;

    cudaFuncSetAttribute(gemm_kernel, cudaFuncAttributeMaxDynamicSharedMemorySize,
                         SMEM_BYTES);

    prep_kernel<<<B_, 256>>>(x, memory, timings, msurp, lastpred);
    gemm_kernel<<<dim3(H_ / BN, B_ / BM, KC), 256, SMEM_BYTES>>>(W1, Wg);
    out_part_kernel<<<dim3(B_ / NB, 4), 256>>>(W2, b1, bg);
    out_reduce_kernel<<<(B_ * V_) / 256, 256>>>(b2, out);
}